// round 1
// baseline (speedup 1.0000x reference)
#include <cuda_runtime.h>
#include <math.h>

#define BB 32
#define NN 3137
#define CC 768
#define HH 12
#define DD 64
#define SCALE 0.125f
#define NPAD 3200
#define SPLITS 10
#define ROWS_PER_SPLIT 314   // 10*314 = 3140 >= 3137

// ---------------- scratch ----------------
__device__ float g_r[BB * HH * CC];              // 1.18 MB : SCALE * q @ Wk, per (b,h) a 768-vec
__device__ float g_s[BB * HH * NPAD];            // 4.9 MB  : scores -> probs (in place)
__device__ float g_up[BB * SPLITS * HH * CC];    // 11.8 MB : partial u accumulators

// ---------------- k1: q projection + r = SCALE * q @ Wk ----------------
__global__ __launch_bounds__(256) void k1_compute_r(
    const float* __restrict__ x, const float* __restrict__ qw,
    const float* __restrict__ qb, const float* __restrict__ kvw)
{
    int b = blockIdx.x;
    int t = threadIdx.x;
    __shared__ float x0[CC];
    __shared__ float qs[CC];

    const float* xrow = x + (size_t)b * NN * CC;   // x[b,0,:]
    for (int i = t; i < CC; i += 256) x0[i] = xrow[i];
    __syncthreads();

    // q[j] = q_b[j] + sum_c x0[c] * q_w[j,c]
    for (int j = t; j < CC; j += 256) {
        const float* w = qw + (size_t)j * CC;
        float acc = qb[j];
        #pragma unroll 8
        for (int c = 0; c < CC; c++) acc += x0[c] * w[c];
        qs[j] = acc;
    }
    __syncthreads();

    // r[h,e] = SCALE * sum_d q[h*64+d] * kv_w[h*64+d, e]
    for (int idx = t; idx < HH * CC; idx += 256) {
        int h = idx / CC, e = idx - h * CC;
        const float* w = kvw + (size_t)(h * DD) * CC + e;
        float acc = 0.f;
        #pragma unroll 8
        for (int d = 0; d < DD; d++) acc += qs[h * DD + d] * w[(size_t)d * CC];
        g_r[(size_t)b * HH * CC + idx] = acc * SCALE;
    }
}

// ---------------- k2: scores s[b,h,n] = r[b,h] . x[b,n] ----------------
// 256 threads = 8 warps; warp owns 4 rows; lane owns a float4 column slice.
__global__ __launch_bounds__(256) void k2_scores(const float* __restrict__ x)
{
    int tile = blockIdx.x;          // 99 tiles of 32 rows
    int b    = blockIdx.y;
    int t = threadIdx.x, warp = t >> 5, lane = t & 31;

    __shared__ float4 rs[HH * (CC / 4)];    // 36 KB, r[h][e/4]
    const float4* rb = (const float4*)(g_r + (size_t)b * HH * CC);
    for (int i = t; i < HH * (CC / 4); i += 256) rs[i] = rb[i];
    __syncthreads();

    int n0 = tile * 32 + warp * 4;
    const float* xb = x + (size_t)b * NN * CC;

    const float4* rowp[4];
    bool v[4];
    #pragma unroll
    for (int rn = 0; rn < 4; rn++) {
        int n = n0 + rn;
        v[rn] = (n < NN);
        rowp[rn] = (const float4*)(xb + (size_t)(v[rn] ? n : 0) * CC);
    }

    float acc[4][HH];
    #pragma unroll
    for (int rn = 0; rn < 4; rn++)
        #pragma unroll
        for (int h = 0; h < HH; h++) acc[rn][h] = 0.f;

    #pragma unroll
    for (int i = 0; i < 6; i++) {
        int cq = i * 32 + lane;             // float4 index within the 768-dim row
        float4 xr[4];
        #pragma unroll
        for (int rn = 0; rn < 4; rn++)
            xr[rn] = v[rn] ? rowp[rn][cq] : make_float4(0.f, 0.f, 0.f, 0.f);
        #pragma unroll
        for (int h = 0; h < HH; h++) {
            float4 rv = rs[h * (CC / 4) + cq];
            #pragma unroll
            for (int rn = 0; rn < 4; rn++) {
                acc[rn][h] += xr[rn].x * rv.x + xr[rn].y * rv.y
                            + xr[rn].z * rv.z + xr[rn].w * rv.w;
            }
        }
    }

    // warp reduce each (rn,h) and store
    #pragma unroll
    for (int rn = 0; rn < 4; rn++) {
        #pragma unroll
        for (int h = 0; h < HH; h++) {
            float s = acc[rn][h];
            s += __shfl_down_sync(0xffffffffu, s, 16);
            s += __shfl_down_sync(0xffffffffu, s, 8);
            s += __shfl_down_sync(0xffffffffu, s, 4);
            s += __shfl_down_sync(0xffffffffu, s, 2);
            s += __shfl_down_sync(0xffffffffu, s, 1);
            if (lane == 0 && v[rn])
                g_s[((size_t)b * HH + h) * NPAD + (n0 + rn)] = s;
        }
    }
}

// ---------------- k3: softmax over n, in place ----------------
__global__ __launch_bounds__(256) void k3_softmax()
{
    int bh = blockIdx.x;                     // 0..383
    float* row = g_s + (size_t)bh * NPAD;
    int t = threadIdx.x;
    __shared__ float red[256];

    float vals[13];
    float m = -1e30f;
    #pragma unroll
    for (int i = 0; i < 13; i++) {
        int n = t + 256 * i;
        vals[i] = (n < NN) ? row[n] : -1e30f;
        m = fmaxf(m, vals[i]);
    }
    red[t] = m; __syncthreads();
    for (int s = 128; s > 0; s >>= 1) {
        if (t < s) red[t] = fmaxf(red[t], red[t + s]);
        __syncthreads();
    }
    m = red[0];
    __syncthreads();

    float sum = 0.f;
    #pragma unroll
    for (int i = 0; i < 13; i++) {
        vals[i] = expf(vals[i] - m);         // exp(-1e30-m) == 0 for padded lanes
        sum += vals[i];
    }
    red[t] = sum; __syncthreads();
    for (int s = 128; s > 0; s >>= 1) {
        if (t < s) red[t] += red[t + s];
        __syncthreads();
    }
    float inv = 1.f / red[0];

    #pragma unroll
    for (int i = 0; i < 13; i++) {
        int n = t + 256 * i;
        if (n < NN) row[n] = vals[i] * inv;
    }
}

// ---------------- k4: u_partial[b,sp,h,:] = sum_n p[b,h,n] * x[b,n,:] ----------------
// 192 threads; thread owns float4 of the e-dim; acc[12] float4 in registers.
__global__ __launch_bounds__(192) void k4_usum(const float* __restrict__ x)
{
    int sp = blockIdx.x, b = blockIdx.y;
    int t = threadIdx.x;                      // 0..191, e0 = 4*t
    int r0 = sp * ROWS_PER_SPLIT;
    int r1 = min(r0 + ROWS_PER_SPLIT, NN);

    __shared__ float ps[HH][64];
    float4 acc[HH];
    #pragma unroll
    for (int h = 0; h < HH; h++) acc[h] = make_float4(0.f, 0.f, 0.f, 0.f);

    const float* xb = x + (size_t)b * NN * CC;

    for (int n0 = r0; n0 < r1; n0 += 64) {
        int cnt = min(64, r1 - n0);
        __syncthreads();
        for (int i = t; i < HH * 64; i += 192) {
            int h = i >> 6, nn = i & 63;
            ps[h][nn] = (nn < cnt)
                      ? g_s[((size_t)b * HH + h) * NPAD + (n0 + nn)] : 0.f;
        }
        __syncthreads();

        for (int nn = 0; nn < cnt; nn++) {
            float4 xv = ((const float4*)(xb + (size_t)(n0 + nn) * CC))[t];
            #pragma unroll
            for (int h = 0; h < HH; h++) {
                float p = ps[h][nn];
                acc[h].x += p * xv.x;
                acc[h].y += p * xv.y;
                acc[h].z += p * xv.z;
                acc[h].w += p * xv.w;
            }
        }
    }

    float* up = g_up + ((size_t)b * SPLITS + sp) * HH * CC;
    #pragma unroll
    for (int h = 0; h < HH; h++)
        ((float4*)(up + h * CC))[t] = acc[h];
}

// ---------------- k5: reduce splits, cls = Wv@u + kv_b_v, out = cls@proj.T + b ----------------
__global__ __launch_bounds__(256) void k5_final(
    const float* __restrict__ kvw, const float* __restrict__ kvb,
    const float* __restrict__ pw,  const float* __restrict__ pb,
    float* __restrict__ out)
{
    int b = blockIdx.x;
    int t = threadIdx.x;
    __shared__ float us[HH * CC];     // 36 KB
    __shared__ float cls[CC];

    for (int i = t; i < HH * CC; i += 256) {
        const float* up = g_up + (size_t)b * SPLITS * HH * CC + i;
        float s = 0.f;
        #pragma unroll
        for (int sp = 0; sp < SPLITS; sp++) s += up[(size_t)sp * HH * CC];
        us[i] = s;
    }
    __syncthreads();

    // cls[j] = kv_b[768+j] + sum_e kv_w[768+j, e] * u[j/64, e]
    for (int j = t; j < CC; j += 256) {
        const float* w = kvw + (size_t)(CC + j) * CC;
        const float* u = us + (j / DD) * CC;
        float acc = kvb[CC + j];
        #pragma unroll 8
        for (int e = 0; e < CC; e++) acc += w[e] * u[e];
        cls[j] = acc;
    }
    __syncthreads();

    // out[b,o] = proj_b[o] + sum_j proj_w[o,j] * cls[j]
    for (int o = t; o < CC; o += 256) {
        const float* w = pw + (size_t)o * CC;
        float acc = pb[o];
        #pragma unroll 8
        for (int j = 0; j < CC; j++) acc += w[j] * cls[j];
        out[(size_t)b * CC + o] = acc;
    }
}

// ---------------- launch ----------------
extern "C" void kernel_launch(void* const* d_in, const int* in_sizes, int n_in,
                              void* d_out, int out_size)
{
    const float* x   = (const float*)d_in[0];
    const float* kvw = (const float*)d_in[1];
    const float* kvb = (const float*)d_in[2];
    const float* qw  = (const float*)d_in[3];
    const float* qb  = (const float*)d_in[4];
    const float* pw  = (const float*)d_in[5];
    const float* pb  = (const float*)d_in[6];
    float* out = (float*)d_out;

    k1_compute_r<<<BB, 256>>>(x, qw, qb, kvw);
    k2_scores<<<dim3((NN + 31) / 32, BB), 256>>>(x);
    k3_softmax<<<BB * HH, 256>>>();
    k4_usum<<<dim3(SPLITS, BB), 192>>>(x);
    k5_final<<<BB, 256>>>(kvw, kvb, pw, pb, out);
}

// round 2
// speedup vs baseline: 5.0882x; 5.0882x over previous
#include <cuda_runtime.h>
#include <math.h>

#define BB 32
#define NN 3137
#define CC 768
#define HH 12
#define DD 64
#define SCALE 0.125f
#define NPAD 3200
#define SPLITS 32
#define ROWS_PER_SPLIT 99    // 32*99 = 3168 >= 3137

// ---------------- scratch ----------------
__device__ float g_q[BB * CC];                   // q projection
__device__ float g_r[BB * HH * CC];              // SCALE * q @ Wk, per (b,h) a 768-vec
__device__ float g_s[BB * HH * NPAD];            // scores -> probs (in place)
__device__ float g_up[BB * SPLITS * HH * CC];    // 37.7 MB partial u accumulators
__device__ float g_u[BB * HH * CC];              // reduced u
__device__ float g_cls[BB * CC];                 // Wv@u + bias_v

__device__ __forceinline__ float warp_sum(float s) {
    s += __shfl_down_sync(0xffffffffu, s, 16);
    s += __shfl_down_sync(0xffffffffu, s, 8);
    s += __shfl_down_sync(0xffffffffu, s, 4);
    s += __shfl_down_sync(0xffffffffu, s, 2);
    s += __shfl_down_sync(0xffffffffu, s, 1);
    return s;
}

// ---------------- k1a: q[b,j] = q_b[j] + x[b,0,:] . q_w[j,:]  (warp per output) ----------------
__global__ __launch_bounds__(256) void k1a_qproj(
    const float* __restrict__ x, const float* __restrict__ qw,
    const float* __restrict__ qb)
{
    int b = blockIdx.y;
    int warp = threadIdx.x >> 5, lane = threadIdx.x & 31;
    int j = blockIdx.x * 8 + warp;                 // 96 * 8 = 768

    const float* xr = x + (size_t)b * NN * CC;     // x[b,0,:]
    const float* w  = qw + (size_t)j * CC;
    float acc = 0.f;
    #pragma unroll
    for (int i = 0; i < CC / 32; i++) {
        int c = i * 32 + lane;
        acc += xr[c] * w[c];
    }
    acc = warp_sum(acc);
    if (lane == 0) g_q[(size_t)b * CC + j] = acc + qb[j];
}

// ---------------- k1b: r[b,h,e] = SCALE * sum_d q[b,h*64+d] * kv_w[h*64+d, e] ----------------
__global__ __launch_bounds__(256) void k1b_r(const float* __restrict__ kvw)
{
    int h = blockIdx.x, b = blockIdx.y;
    int t = threadIdx.x;
    __shared__ float qs[DD];
    if (t < DD) qs[t] = g_q[(size_t)b * CC + h * DD + t];
    __syncthreads();

    float acc0 = 0.f, acc1 = 0.f, acc2 = 0.f;
    const float* w = kvw + (size_t)(h * DD) * CC;
    #pragma unroll 8
    for (int d = 0; d < DD; d++) {
        float qd = qs[d];
        const float* wr = w + (size_t)d * CC;
        acc0 += qd * wr[t];
        acc1 += qd * wr[t + 256];
        acc2 += qd * wr[t + 512];
    }
    float* r = g_r + ((size_t)b * HH + h) * CC;
    r[t]       = acc0 * SCALE;
    r[t + 256] = acc1 * SCALE;
    r[t + 512] = acc2 * SCALE;
}

// ---------------- k2: scores s[b,h,n] = r[b,h] . x[b,n] ----------------
__global__ __launch_bounds__(256) void k2_scores(const float* __restrict__ x)
{
    int tile = blockIdx.x;          // 99 tiles of 32 rows
    int b    = blockIdx.y;
    int t = threadIdx.x, warp = t >> 5, lane = t & 31;

    __shared__ float4 rs[HH * (CC / 4)];    // 36 KB
    const float4* rb = (const float4*)(g_r + (size_t)b * HH * CC);
    for (int i = t; i < HH * (CC / 4); i += 256) rs[i] = rb[i];
    __syncthreads();

    int n0 = tile * 32 + warp * 4;
    const float* xb = x + (size_t)b * NN * CC;

    const float4* rowp[4];
    bool v[4];
    #pragma unroll
    for (int rn = 0; rn < 4; rn++) {
        int n = n0 + rn;
        v[rn] = (n < NN);
        rowp[rn] = (const float4*)(xb + (size_t)(v[rn] ? n : 0) * CC);
    }

    float acc[4][HH];
    #pragma unroll
    for (int rn = 0; rn < 4; rn++)
        #pragma unroll
        for (int h = 0; h < HH; h++) acc[rn][h] = 0.f;

    #pragma unroll
    for (int i = 0; i < 6; i++) {
        int cq = i * 32 + lane;
        float4 xr[4];
        #pragma unroll
        for (int rn = 0; rn < 4; rn++)
            xr[rn] = v[rn] ? rowp[rn][cq] : make_float4(0.f, 0.f, 0.f, 0.f);
        #pragma unroll
        for (int h = 0; h < HH; h++) {
            float4 rv = rs[h * (CC / 4) + cq];
            #pragma unroll
            for (int rn = 0; rn < 4; rn++) {
                acc[rn][h] += xr[rn].x * rv.x + xr[rn].y * rv.y
                            + xr[rn].z * rv.z + xr[rn].w * rv.w;
            }
        }
    }

    #pragma unroll
    for (int rn = 0; rn < 4; rn++) {
        #pragma unroll
        for (int h = 0; h < HH; h++) {
            float s = warp_sum(acc[rn][h]);
            if (lane == 0 && v[rn])
                g_s[((size_t)b * HH + h) * NPAD + (n0 + rn)] = s;
        }
    }
}

// ---------------- k3: softmax over n, in place ----------------
__global__ __launch_bounds__(256) void k3_softmax()
{
    int bh = blockIdx.x;
    float* row = g_s + (size_t)bh * NPAD;
    int t = threadIdx.x;
    __shared__ float red[256];

    float vals[13];
    float m = -1e30f;
    #pragma unroll
    for (int i = 0; i < 13; i++) {
        int n = t + 256 * i;
        vals[i] = (n < NN) ? row[n] : -1e30f;
        m = fmaxf(m, vals[i]);
    }
    red[t] = m; __syncthreads();
    for (int s = 128; s > 0; s >>= 1) {
        if (t < s) red[t] = fmaxf(red[t], red[t + s]);
        __syncthreads();
    }
    m = red[0];
    __syncthreads();

    float sum = 0.f;
    #pragma unroll
    for (int i = 0; i < 13; i++) {
        vals[i] = expf(vals[i] - m);
        sum += vals[i];
    }
    red[t] = sum; __syncthreads();
    for (int s = 128; s > 0; s >>= 1) {
        if (t < s) red[t] += red[t + s];
        __syncthreads();
    }
    float inv = 1.f / red[0];

    #pragma unroll
    for (int i = 0; i < 13; i++) {
        int n = t + 256 * i;
        if (n < NN) row[n] = vals[i] * inv;
    }
}

// ---------------- k4: u_partial[b,sp,h,:] = sum_n p[b,h,n] * x[b,n,:] ----------------
__global__ __launch_bounds__(192) void k4_usum(const float* __restrict__ x)
{
    int sp = blockIdx.x, b = blockIdx.y;
    int t = threadIdx.x;                      // 0..191, e0 = 4*t
    int r0 = sp * ROWS_PER_SPLIT;
    int r1 = min(r0 + ROWS_PER_SPLIT, NN);

    __shared__ float ps[HH][64];
    float4 acc[HH];
    #pragma unroll
    for (int h = 0; h < HH; h++) acc[h] = make_float4(0.f, 0.f, 0.f, 0.f);

    const float* xb = x + (size_t)b * NN * CC;

    for (int n0 = r0; n0 < r1; n0 += 64) {
        int cnt = min(64, r1 - n0);
        __syncthreads();
        for (int i = t; i < HH * 64; i += 192) {
            int h = i >> 6, nn = i & 63;
            ps[h][nn] = (nn < cnt)
                      ? g_s[((size_t)b * HH + h) * NPAD + (n0 + nn)] : 0.f;
        }
        __syncthreads();

        int nn = 0;
        for (; nn + 2 <= cnt; nn += 2) {
            float4 xv0 = ((const float4*)(xb + (size_t)(n0 + nn) * CC))[t];
            float4 xv1 = ((const float4*)(xb + (size_t)(n0 + nn + 1) * CC))[t];
            #pragma unroll
            for (int h = 0; h < HH; h++) {
                float p0 = ps[h][nn], p1 = ps[h][nn + 1];
                acc[h].x += p0 * xv0.x + p1 * xv1.x;
                acc[h].y += p0 * xv0.y + p1 * xv1.y;
                acc[h].z += p0 * xv0.z + p1 * xv1.z;
                acc[h].w += p0 * xv0.w + p1 * xv1.w;
            }
        }
        for (; nn < cnt; nn++) {
            float4 xv = ((const float4*)(xb + (size_t)(n0 + nn) * CC))[t];
            #pragma unroll
            for (int h = 0; h < HH; h++) {
                float p = ps[h][nn];
                acc[h].x += p * xv.x;
                acc[h].y += p * xv.y;
                acc[h].z += p * xv.z;
                acc[h].w += p * xv.w;
            }
        }
    }

    float* up = g_up + ((size_t)b * SPLITS + sp) * HH * CC;
    #pragma unroll
    for (int h = 0; h < HH; h++)
        ((float4*)(up + h * CC))[t] = acc[h];
}

// ---------------- k5a: u[b,:] = sum_sp u_partial[b,sp,:] ----------------
__global__ __launch_bounds__(256) void k5a_reduce()
{
    int b = blockIdx.y;
    int idx = blockIdx.x * 256 + threadIdx.x;        // 36 blocks * 256 = 9216
    const float* up = g_up + (size_t)b * SPLITS * HH * CC + idx;
    float s = 0.f;
    #pragma unroll 8
    for (int sp = 0; sp < SPLITS; sp++) s += up[(size_t)sp * HH * CC];
    g_u[(size_t)b * HH * CC + idx] = s;
}

// ---------------- k5b: cls[b,j] = kv_b[C+j] + kv_w[C+j,:] . u[b, j/64, :] ----------------
__global__ __launch_bounds__(256) void k5b_v(
    const float* __restrict__ kvw, const float* __restrict__ kvb)
{
    int b = blockIdx.y;
    int warp = threadIdx.x >> 5, lane = threadIdx.x & 31;
    int j = blockIdx.x * 8 + warp;

    const float* w = kvw + (size_t)(CC + j) * CC;
    const float* u = g_u + (size_t)b * HH * CC + (j / DD) * CC;
    float acc = 0.f;
    #pragma unroll
    for (int i = 0; i < CC / 32; i++) {
        int e = i * 32 + lane;
        acc += w[e] * u[e];
    }
    acc = warp_sum(acc);
    if (lane == 0) g_cls[(size_t)b * CC + j] = acc + kvb[CC + j];
}

// ---------------- k5c: out[b,o] = proj_b[o] + proj_w[o,:] . cls[b,:] ----------------
__global__ __launch_bounds__(256) void k5c_proj(
    const float* __restrict__ pw, const float* __restrict__ pb,
    float* __restrict__ out)
{
    int b = blockIdx.y;
    int warp = threadIdx.x >> 5, lane = threadIdx.x & 31;
    int o = blockIdx.x * 8 + warp;

    const float* w = pw + (size_t)o * CC;
    const float* c = g_cls + (size_t)b * CC;
    float acc = 0.f;
    #pragma unroll
    for (int i = 0; i < CC / 32; i++) {
        int j = i * 32 + lane;
        acc += w[j] * c[j];
    }
    acc = warp_sum(acc);
    if (lane == 0) out[(size_t)b * CC + o] = acc + pb[o];
}

// ---------------- launch ----------------
extern "C" void kernel_launch(void* const* d_in, const int* in_sizes, int n_in,
                              void* d_out, int out_size)
{
    const float* x   = (const float*)d_in[0];
    const float* kvw = (const float*)d_in[1];
    const float* kvb = (const float*)d_in[2];
    const float* qw  = (const float*)d_in[3];
    const float* qb  = (const float*)d_in[4];
    const float* pw  = (const float*)d_in[5];
    const float* pb  = (const float*)d_in[6];
    float* out = (float*)d_out;

    k1a_qproj<<<dim3(96, BB), 256>>>(x, qw, qb);
    k1b_r<<<dim3(HH, BB), 256>>>(kvw);
    k2_scores<<<dim3((NN + 31) / 32, BB), 256>>>(x);
    k3_softmax<<<BB * HH, 256>>>();
    k4_usum<<<dim3(SPLITS, BB), 192>>>(x);
    k5a_reduce<<<dim3(36, BB), 256>>>();
    k5b_v<<<dim3(96, BB), 256>>>(kvw, kvb);
    k5c_proj<<<dim3(96, BB), 256>>>(pw, pb, out);
}